// round 9
// baseline (speedup 1.0000x reference)
#include <cuda_runtime.h>
#include <cuda_bf16.h>
#include <cstdint>
#include <cstddef>

// ---------------- problem constants ----------------
#define D_MODEL 1024
#define N_LAYER 4
#define VOCAB   32000
#define D_STATE 16
#define D_INNER 2048
#define D_CONV  4
#define BATCH   2
#define SEQ     1024
#define M_ROWS  (BATCH * SEQ)     // 2048

// ---------------- scratch (device globals; no allocation allowed) ----------
__device__ float g_X  [M_ROWS * D_MODEL];
__device__ float g_H  [M_ROWS * D_INNER];
__device__ float g_RES[M_ROWS * D_INNER];
__device__ float g_U  [M_ROWS * D_INNER];
__device__ float g_B  [M_ROWS * D_STATE];
__device__ float g_C  [M_ROWS * D_STATE];
__device__ float g_dt [M_ROWS];

// bf16 hi/lo operand buffers
__device__ __nv_bfloat16 g_XNh[M_ROWS * D_MODEL], g_XNl[M_ROWS * D_MODEL];
__device__ __nv_bfloat16 g_Hh [M_ROWS * D_INNER], g_Hl [M_ROWS * D_INNER];
__device__ __nv_bfloat16 g_YRh[M_ROWS * D_INNER], g_YRl[M_ROWS * D_INNER];
__device__ __nv_bfloat16 g_Winh [N_LAYER * D_INNER * D_MODEL], g_Winl [N_LAYER * D_INNER * D_MODEL];
__device__ __nv_bfloat16 g_Wresh[N_LAYER * D_INNER * D_INNER], g_Wresl[N_LAYER * D_INNER * D_INNER];
__device__ __nv_bfloat16 g_Wouth[N_LAYER * D_MODEL * D_INNER], g_Woutl[N_LAYER * D_MODEL * D_INNER];
__device__ __nv_bfloat16 g_Embh [(size_t)VOCAB * D_MODEL],     g_Embl [(size_t)VOCAB * D_MODEL];

// ---------------- small helpers ----------------
__device__ __forceinline__ float silu_f(float x) { return x / (1.f + __expf(-x)); }
__device__ __forceinline__ float softplus_f(float x) { return x > 20.f ? x : log1pf(__expf(x)); }

__device__ __forceinline__ uint32_t smem_addr_u32(const void* p) {
    uint32_t a;
    asm("{ .reg .u64 t; cvta.to.shared.u64 t, %1; cvt.u32.u64 %0, t; }" : "=r"(a) : "l"(p));
    return a;
}
__device__ __forceinline__ void cp16(uint32_t dst, const void* src) {
    asm volatile("cp.async.cg.shared.global [%0], [%1], 16;" :: "r"(dst), "l"(src));
}
__device__ __forceinline__ void cp_commit() {
    asm volatile("cp.async.commit_group;" ::: "memory");
}
template <int N>
__device__ __forceinline__ void cp_wait() {
    asm volatile("cp.async.wait_group %0;" :: "n"(N) : "memory");
}
__device__ __forceinline__ void ldsm4(uint32_t& r0, uint32_t& r1, uint32_t& r2, uint32_t& r3,
                                      uint32_t a) {
    asm volatile("ldmatrix.sync.aligned.m8n8.x4.shared.b16 {%0,%1,%2,%3}, [%4];"
                 : "=r"(r0), "=r"(r1), "=r"(r2), "=r"(r3) : "r"(a));
}
__device__ __forceinline__ void mma_bf16(float& d0, float& d1, float& d2, float& d3,
                                         uint32_t a0, uint32_t a1, uint32_t a2, uint32_t a3,
                                         uint32_t b0, uint32_t b1) {
    asm volatile(
        "mma.sync.aligned.m16n8k16.row.col.f32.bf16.bf16.f32 "
        "{%0,%1,%2,%3}, {%4,%5,%6,%7}, {%8,%9}, {%0,%1,%2,%3};"
        : "+f"(d0), "+f"(d1), "+f"(d2), "+f"(d3)
        : "r"(a0), "r"(a1), "r"(a2), "r"(a3), "r"(b0), "r"(b1));
}
__device__ __forceinline__ void split_bf16(float v, __nv_bfloat16& hi, __nv_bfloat16& lo) {
    hi = __float2bfloat16(v);
    lo = __float2bfloat16(v - __bfloat162float(hi));
}

// ---------------- fp32 -> bf16 hi/lo split (weights) --------------
__global__ void split_kernel(const float4* __restrict__ x,
                             __nv_bfloat162* __restrict__ hi,
                             __nv_bfloat162* __restrict__ lo, int n4) {
    int t = blockIdx.x * 256 + threadIdx.x;
    if (t >= n4) return;
    float4 v = x[t];
    __nv_bfloat16 a = __float2bfloat16(v.x), b = __float2bfloat16(v.y);
    __nv_bfloat16 c = __float2bfloat16(v.z), d = __float2bfloat16(v.w);
    hi[2 * t]     = __nv_bfloat162(a, b);
    hi[2 * t + 1] = __nv_bfloat162(c, d);
    lo[2 * t] = __nv_bfloat162(__float2bfloat16(v.x - __bfloat162float(a)),
                               __float2bfloat16(v.y - __bfloat162float(b)));
    lo[2 * t + 1] = __nv_bfloat162(__float2bfloat16(v.z - __bfloat162float(c)),
                                   __float2bfloat16(v.w - __bfloat162float(d)));
}

// ---------------- embedding gather ----------------
__global__ void embed_kernel(const float* __restrict__ emb,
                             const int* __restrict__ ids,
                             float* __restrict__ X) {
    int t = blockIdx.x * blockDim.x + threadIdx.x;
    int row = t >> 10, col = t & 1023;
    X[t] = emb[(size_t)ids[row] * D_MODEL + col];
}

// ---------------- rmsnorm -> bf16 hi/lo directly ----------------
__global__ void rmsnorm_kernel(const float* __restrict__ X,
                               const float* __restrict__ w,
                               __nv_bfloat16* __restrict__ outh,
                               __nv_bfloat16* __restrict__ outl) {
    int row = blockIdx.x;
    const float* x = X + (size_t)row * D_MODEL;
    float s = 0.f;
    for (int i = threadIdx.x; i < D_MODEL; i += 256) { float v = x[i]; s += v * v; }
    __shared__ float red[256];
    red[threadIdx.x] = s;
    __syncthreads();
    for (int o = 128; o; o >>= 1) {
        if (threadIdx.x < o) red[threadIdx.x] += red[threadIdx.x + o];
        __syncthreads();
    }
    float scale = rsqrtf(red[0] * (1.f / D_MODEL) + 1e-5f);
    for (int i = threadIdx.x; i < D_MODEL; i += 256) {
        float v = x[i] * scale * w[i];
        __nv_bfloat16 hi, lo;
        split_bf16(v, hi, lo);
        outh[(size_t)row * D_MODEL + i] = hi;
        outl[(size_t)row * D_MODEL + i] = lo;
    }
}

// ---------------- depthwise causal conv + silu ----------------
__global__ void conv_kernel(const float* __restrict__ H,
                            const float* __restrict__ cw,
                            const float* __restrict__ cb,
                            float* __restrict__ Uo) {
    int t = blockIdx.x * blockDim.x + threadIdx.x;
    int d = t & (D_INNER - 1);
    int bl = t >> 11;
    int l = bl & (SEQ - 1);
    float acc = cb[d];
#pragma unroll
    for (int j = 0; j < D_CONV; j++) {
        int ll = l - (D_CONV - 1) + j;
        if (ll >= 0)
            acc += H[(size_t)(bl - l + ll) * D_INNER + d] * cw[d * D_CONV + j];
    }
    Uo[t] = silu_f(acc);
}

// ---------------- B, C, dt projections: 8 rows per CTA ----------------
#define BC_ROWS 8
#define BC_SMEM (BC_ROWS * D_INNER * 4)   // 65536 B

__global__ void __launch_bounds__(256) bc_kernel(
    const float* __restrict__ U,
    const float* __restrict__ wB, const float* __restrict__ bB,
    const float* __restrict__ wC, const float* __restrict__ bC,
    const float* __restrict__ wdt, const float* __restrict__ bdt,
    float* __restrict__ Bm, float* __restrict__ Cm,
    float* __restrict__ dtb) {
    extern __shared__ float su[];             // [BC_ROWS][D_INNER]
    int row0 = blockIdx.x * BC_ROWS;
    int tid = threadIdx.x;
    const float4* Uv = (const float4*)(U + (size_t)row0 * D_INNER);
    float4* sv = (float4*)su;
    for (int i = tid; i < BC_ROWS * D_INNER / 4; i += 256)
        sv[i] = Uv[i];
    __syncthreads();
    int warp = tid >> 5, lane = tid & 31;
    for (int j = warp; j < 2 * D_STATE + 1; j += 8) {
        const float* w = (j < D_STATE) ? wB + (size_t)j * D_INNER
                       : (j < 2 * D_STATE) ? wC + (size_t)(j - D_STATE) * D_INNER
                       : wdt;
        float acc[BC_ROWS];
#pragma unroll
        for (int r = 0; r < BC_ROWS; r++) acc[r] = 0.f;
        for (int k = lane; k < D_INNER; k += 32) {
            float wv = w[k];
#pragma unroll
            for (int r = 0; r < BC_ROWS; r++)
                acc[r] += su[r * D_INNER + k] * wv;
        }
#pragma unroll
        for (int r = 0; r < BC_ROWS; r++) {
#pragma unroll
            for (int o = 16; o; o >>= 1)
                acc[r] += __shfl_down_sync(0xffffffffu, acc[r], o);
        }
        if (lane == 0) {
#pragma unroll
            for (int r = 0; r < BC_ROWS; r++) {
                int bl = row0 + r;
                if (j < D_STATE)          Bm[bl * D_STATE + j] = acc[r] + bB[j];
                else if (j < 2 * D_STATE) Cm[bl * D_STATE + (j - D_STATE)] = acc[r] + bC[j - D_STATE];
                else                      dtb[bl] = acc[r] + bdt[0];
            }
        }
    }
}

// ---------------- selective scan: 2 threads per d, writes bf16 hi/lo ----
__global__ void scan_kernel(const float* __restrict__ U,
                            const float* __restrict__ RES,
                            const float* __restrict__ Bm,
                            const float* __restrict__ Cm,
                            const float* __restrict__ dtb,
                            const float* __restrict__ A_log,
                            const float* __restrict__ tau,
                            const float* __restrict__ Dp,
                            __nv_bfloat16* __restrict__ YRh,
                            __nv_bfloat16* __restrict__ YRl) {
    int td = blockIdx.x * 256 + threadIdx.x;   // 0 .. 2*D_INNER-1
    int d = td >> 1;
    int half = td & 1;
    int b = blockIdx.y;

    float a[8], h[8];
#pragma unroll
    for (int n = 0; n < 8; n++) {
        a[n] = -__expf(A_log[(size_t)d * D_STATE + half * 8 + n]);
        h[n] = 0.f;
    }
    float tau_d = tau[d], dpv = Dp[d];
    size_t rowbase = (size_t)b * SEQ;

    for (int l = 0; l < SEQ; l++) {
        size_t bl = rowbase + l;
        float delta = softplus_f(tau_d + dtb[bl]);
        float u = U[bl * D_INNER + d];
        float du = delta * u;
        const float* Bp = Bm + bl * D_STATE + half * 8;
        const float* Cp = Cm + bl * D_STATE + half * 8;
        float y0 = 0.f, y1 = 0.f;
#pragma unroll
        for (int n = 0; n < 8; n++) {
            float da = __expf(delta * a[n]);
            h[n] = da * h[n] + du * Bp[n];
            float yy = Cp[n] * h[n];
            if (n & 1) y1 += yy; else y0 += yy;
        }
        float y = y0 + y1;
        y += __shfl_xor_sync(0xffffffffu, y, 1);
        if (half == 0) {
            float v = (y + dpv * u) * RES[bl * D_INNER + d];
            __nv_bfloat16 hi, lo;
            split_bf16(v, hi, lo);
            YRh[bl * D_INNER + d] = hi;
            YRl[bl * D_INNER + d] = lo;
        }
    }
}

// ---------------- bf16x3 HMMA GEMM: C = A*W^T (+bias, epilogue) ---------
// CTA 128x128x32, 8 warps (4m x 2n), warp tile 32x64 via m16n8k16.
// B fragments double-buffered in registers: LDSM for p+1 overlaps MMAs of p.
// EPI: 0 store fp32, 1 silu fp32, 2 accumulate fp32, 3 fp32 + bf16 hi/lo
#define HBM 128
#define HBN 128
#define HBK 32
#define HSTR 40                      // halves per smem row (32 + 8 pad) = 80B
#define A_TILE (HBM * HSTR)          // 5120 halves
#define W_TILE (HBN * HSTR)          // 5120 halves
#define OFF_AH 0
#define OFF_AL (2 * A_TILE)
#define OFF_WH (4 * A_TILE)
#define OFF_WL (4 * A_TILE + 2 * W_TILE)
#define HG_SMEM ((4 * A_TILE + 4 * W_TILE) * 2)   // 81920 B

__device__ __forceinline__ void hfill(const __nv_bfloat16* __restrict__ Ah,
                                      const __nv_bfloat16* __restrict__ Al,
                                      const __nv_bfloat16* __restrict__ Wh,
                                      const __nv_bfloat16* __restrict__ Wl,
                                      int m0, int n0, int K, int k0,
                                      uint32_t smem_u, int stage, int tid) {
    uint32_t baseAh = smem_u + (OFF_AH + stage * A_TILE) * 2;
    uint32_t baseAl = smem_u + (OFF_AL + stage * A_TILE) * 2;
    uint32_t baseWh = smem_u + (OFF_WH + stage * W_TILE) * 2;
    uint32_t baseWl = smem_u + (OFF_WL + stage * W_TILE) * 2;
#pragma unroll
    for (int t = 0; t < 2; t++) {
        int idx = tid + t * 256;            // 0..511 : 128 rows x 4 chunks of 8 halves
        int r = idx >> 2, c = idx & 3;
        size_t go = (size_t)(m0 + r) * K + k0 + c * 8;
        uint32_t so = (uint32_t)(r * HSTR + c * 8) * 2;
        cp16(baseAh + so, Ah + go);
        cp16(baseAl + so, Al + go);
    }
#pragma unroll
    for (int t = 0; t < 2; t++) {
        int idx = tid + t * 256;            // 0..511 : 128 rows x 4 chunks
        int r = idx >> 2, c = idx & 3;
        size_t go = (size_t)(n0 + r) * K + k0 + c * 8;
        uint32_t so = (uint32_t)(r * HSTR + c * 8) * 2;
        cp16(baseWh + so, Wh + go);
        cp16(baseWl + so, Wl + go);
    }
}

template <int EPI>
__global__ void __launch_bounds__(256, 2) hgemm_kernel(
    const __nv_bfloat16* __restrict__ Ah, const __nv_bfloat16* __restrict__ Al,
    const __nv_bfloat16* __restrict__ Wh, const __nv_bfloat16* __restrict__ Wl,
    const float* __restrict__ bias, float* __restrict__ C,
    __nv_bfloat16* __restrict__ Chi, __nv_bfloat16* __restrict__ Clo,
    int M, int N, int K) {
    extern __shared__ __nv_bfloat16 hsm[];
    const uint32_t smem_u = smem_addr_u32(hsm);

    const int tid = threadIdx.x;
    const int wid = tid >> 5;
    const int lane = tid & 31;
    const int wm = wid & 3;       // 0..3: 32 m-rows each
    const int wn = wid >> 2;      // 0..1: 64 n-cols each
    const int m0 = blockIdx.y * HBM;
    const int n0 = blockIdx.x * HBN;

    const int arow = wm * 32 + (lane & 15);
    const int acol = (lane >> 4) * 8;
    const int brow = wn * 64 + (lane & 7) + ((lane >> 4) << 3);
    const int bcol = ((lane >> 3) & 1) * 8;

    float acc[2][8][4];
#pragma unroll
    for (int i = 0; i < 2; i++)
#pragma unroll
        for (int j = 0; j < 8; j++)
#pragma unroll
            for (int v = 0; v < 4; v++) acc[i][j][v] = 0.f;

    const int nb = K / HBK;
    hfill(Ah, Al, Wh, Wl, m0, n0, K, 0, smem_u, 0, tid);
    cp_commit();

    int buf = 0;
    for (int kb = 0; kb < nb; kb++) {
        if (kb + 1 < nb) {
            hfill(Ah, Al, Wh, Wl, m0, n0, K, (kb + 1) * HBK, smem_u, buf ^ 1, tid);
            cp_commit();
            cp_wait<1>();
        } else {
            cp_wait<0>();
        }
        __syncthreads();

        const uint32_t bAh = smem_u + (OFF_AH + buf * A_TILE) * 2;
        const uint32_t bAl = smem_u + (OFF_AL + buf * A_TILE) * 2;
        const uint32_t bWh = smem_u + (OFF_WH + buf * W_TILE) * 2;
        const uint32_t bWl = smem_u + (OFF_WL + buf * W_TILE) * 2;

#pragma unroll
        for (int kk = 0; kk < HBK; kk += 16) {
            uint32_t fah[2][4], fal[2][4];
#pragma unroll
            for (int mt = 0; mt < 2; mt++) {
                uint32_t off = (uint32_t)((arow + mt * 16) * HSTR + kk + acol) * 2;
                ldsm4(fah[mt][0], fah[mt][1], fah[mt][2], fah[mt][3], bAh + off);
                ldsm4(fal[mt][0], fal[mt][1], fal[mt][2], fal[mt][3], bAl + off);
            }
            // B register double buffer: preload p=0
            uint32_t bh[2][4], bl_[2][4];
            {
                uint32_t off = (uint32_t)(brow * HSTR + kk + bcol) * 2;
                ldsm4(bh[0][0], bh[0][1], bh[0][2], bh[0][3], bWh + off);
                ldsm4(bl_[0][0], bl_[0][1], bl_[0][2], bl_[0][3], bWl + off);
            }
#pragma unroll
            for (int p = 0; p < 4; p++) {      // 4 groups of 16 n-rows
                const int cur = p & 1;
                if (p < 3) {
                    uint32_t off = (uint32_t)((brow + (p + 1) * 16) * HSTR + kk + bcol) * 2;
                    ldsm4(bh[cur ^ 1][0], bh[cur ^ 1][1], bh[cur ^ 1][2], bh[cur ^ 1][3], bWh + off);
                    ldsm4(bl_[cur ^ 1][0], bl_[cur ^ 1][1], bl_[cur ^ 1][2], bl_[cur ^ 1][3], bWl + off);
                }
#pragma unroll
                for (int mt = 0; mt < 2; mt++) {
                    float* d0 = acc[mt][p * 2];
                    float* d1 = acc[mt][p * 2 + 1];
                    mma_bf16(d0[0], d0[1], d0[2], d0[3],
                             fah[mt][0], fah[mt][1], fah[mt][2], fah[mt][3],
                             bh[cur][0], bh[cur][1]);
                    mma_bf16(d0[0], d0[1], d0[2], d0[3],
                             fal[mt][0], fal[mt][1], fal[mt][2], fal[mt][3],
                             bh[cur][0], bh[cur][1]);
                    mma_bf16(d0[0], d0[1], d0[2], d0[3],
                             fah[mt][0], fah[mt][1], fah[mt][2], fah[mt][3],
                             bl_[cur][0], bl_[cur][1]);
                    mma_bf16(d1[0], d1[1], d1[2], d1[3],
                             fah[mt][0], fah[mt][1], fah[mt][2], fah[mt][3],
                             bh[cur][2], bh[cur][3]);
                    mma_bf16(d1[0], d1[1], d1[2], d1[3],
                             fal[mt][0], fal[mt][1], fal[mt][2], fal[mt][3],
                             bh[cur][2], bh[cur][3]);
                    mma_bf16(d1[0], d1[1], d1[2], d1[3],
                             fah[mt][0], fah[mt][1], fah[mt][2], fah[mt][3],
                             bl_[cur][2], bl_[cur][3]);
                }
            }
        }
        __syncthreads();
        buf ^= 1;
    }

    // ---- epilogue ----
    const int g = lane >> 2, tg = lane & 3;
#pragma unroll
    for (int mt = 0; mt < 2; mt++) {
#pragma unroll
        for (int nt = 0; nt < 8; nt++) {
            int m = m0 + wm * 32 + mt * 16 + g;
            int n = n0 + wn * 64 + nt * 8 + tg * 2;
            float b0 = bias ? bias[n] : 0.f;
            float b1 = bias ? bias[n + 1] : 0.f;
#pragma unroll
            for (int half = 0; half < 2; half++) {
                int mm = m + half * 8;
                float v0 = acc[mt][nt][half * 2 + 0] + b0;
                float v1 = acc[mt][nt][half * 2 + 1] + b1;
                if (EPI == 1) { v0 = silu_f(v0); v1 = silu_f(v1); }
                size_t off = (size_t)mm * N + n;
                if (EPI == 2) { C[off] += v0; C[off + 1] += v1; }
                else          { C[off] = v0;  C[off + 1] = v1; }
                if (EPI == 3) {
                    __nv_bfloat16 h0, l0, h1, l1;
                    split_bf16(v0, h0, l0);
                    split_bf16(v1, h1, l1);
                    Chi[off] = h0; Chi[off + 1] = h1;
                    Clo[off] = l0; Clo[off + 1] = l1;
                }
            }
        }
    }
}

// ---------------- launch ----------------
static inline void split_launch(const float* src, __nv_bfloat16* hi, __nv_bfloat16* lo, size_t n) {
    int n4 = (int)(n / 4);
    split_kernel<<<(n4 + 255) / 256, 256>>>((const float4*)src, (__nv_bfloat162*)hi,
                                            (__nv_bfloat162*)lo, n4);
}

extern "C" void kernel_launch(void* const* d_in, const int* in_sizes, int n_in,
                              void* d_out, int out_size) {
    const float* emb    = (const float*)d_in[0];
    const float* norm_w = (const float*)d_in[1];
    const float* w_in   = (const float*)d_in[2];
    const float* b_in   = (const float*)d_in[3];
    const float* w_res  = (const float*)d_in[4];
    const float* b_res  = (const float*)d_in[5];
    const float* conv_w = (const float*)d_in[6];
    const float* conv_b = (const float*)d_in[7];
    const float* w_B    = (const float*)d_in[8];
    const float* b_B    = (const float*)d_in[9];
    const float* w_C    = (const float*)d_in[10];
    const float* b_C    = (const float*)d_in[11];
    const float* w_dt   = (const float*)d_in[12];
    const float* b_dt   = (const float*)d_in[13];
    const float* tau_dt = (const float*)d_in[14];
    const float* A_log  = (const float*)d_in[15];
    const float* Dp     = (const float*)d_in[16];
    const float* w_out  = (const float*)d_in[17];
    const float* b_out  = (const float*)d_in[18];
    const float* fnw    = (const float*)d_in[19];
    const int*   ids    = (const int*)d_in[20];
    float* out = (float*)d_out;

    cudaFuncSetAttribute(hgemm_kernel<0>, cudaFuncAttributeMaxDynamicSharedMemorySize, HG_SMEM);
    cudaFuncSetAttribute(hgemm_kernel<1>, cudaFuncAttributeMaxDynamicSharedMemorySize, HG_SMEM);
    cudaFuncSetAttribute(hgemm_kernel<2>, cudaFuncAttributeMaxDynamicSharedMemorySize, HG_SMEM);
    cudaFuncSetAttribute(hgemm_kernel<3>, cudaFuncAttributeMaxDynamicSharedMemorySize, HG_SMEM);
    cudaFuncSetAttribute(bc_kernel, cudaFuncAttributeMaxDynamicSharedMemorySize, BC_SMEM);

    float *pX, *pH, *pRES, *pU, *pB, *pC, *pDT;
    cudaGetSymbolAddress((void**)&pX, g_X);
    cudaGetSymbolAddress((void**)&pH, g_H);
    cudaGetSymbolAddress((void**)&pRES, g_RES);
    cudaGetSymbolAddress((void**)&pU, g_U);
    cudaGetSymbolAddress((void**)&pB, g_B);
    cudaGetSymbolAddress((void**)&pC, g_C);
    cudaGetSymbolAddress((void**)&pDT, g_dt);

    __nv_bfloat16 *pXNh, *pXNl, *pHh, *pHl, *pYRh, *pYRl;
    __nv_bfloat16 *pWinh, *pWinl, *pWresh, *pWresl, *pWouth, *pWoutl, *pEmbh, *pEmbl;
    cudaGetSymbolAddress((void**)&pXNh, g_XNh);  cudaGetSymbolAddress((void**)&pXNl, g_XNl);
    cudaGetSymbolAddress((void**)&pHh, g_Hh);    cudaGetSymbolAddress((void**)&pHl, g_Hl);
    cudaGetSymbolAddress((void**)&pYRh, g_YRh);  cudaGetSymbolAddress((void**)&pYRl, g_YRl);
    cudaGetSymbolAddress((void**)&pWinh, g_Winh);   cudaGetSymbolAddress((void**)&pWinl, g_Winl);
    cudaGetSymbolAddress((void**)&pWresh, g_Wresh); cudaGetSymbolAddress((void**)&pWresl, g_Wresl);
    cudaGetSymbolAddress((void**)&pWouth, g_Wouth); cudaGetSymbolAddress((void**)&pWoutl, g_Woutl);
    cudaGetSymbolAddress((void**)&pEmbh, g_Embh);   cudaGetSymbolAddress((void**)&pEmbl, g_Embl);

    // weight conversions (all layers at once)
    split_launch(emb,   pEmbh,  pEmbl,  (size_t)VOCAB * D_MODEL);
    split_launch(w_in,  pWinh,  pWinl,  (size_t)N_LAYER * D_INNER * D_MODEL);
    split_launch(w_res, pWresh, pWresl, (size_t)N_LAYER * D_INNER * D_INNER);
    split_launch(w_out, pWouth, pWoutl, (size_t)N_LAYER * D_MODEL * D_INNER);

    embed_kernel<<<(M_ROWS * D_MODEL) / 256, 256>>>(emb, ids, pX);

    for (int i = 0; i < N_LAYER; i++) {
        const float* bi  = b_in   + (size_t)i * D_INNER;
        const float* br  = b_res  + (size_t)i * D_INNER;
        const float* cw  = conv_w + (size_t)i * D_INNER * D_CONV;
        const float* cb  = conv_b + (size_t)i * D_INNER;
        const float* wB  = w_B  + (size_t)i * D_STATE * D_INNER;
        const float* bB  = b_B  + (size_t)i * D_STATE;
        const float* wC  = w_C  + (size_t)i * D_STATE * D_INNER;
        const float* bC  = b_C  + (size_t)i * D_STATE;
        const float* wdt = w_dt + (size_t)i * D_INNER;
        const float* bdt = b_dt + (size_t)i;
        const float* tau = tau_dt + (size_t)i * D_INNER;
        const float* Al  = A_log + (size_t)i * D_INNER * D_STATE;
        const float* dp  = Dp    + (size_t)i * D_INNER;
        const float* bo  = b_out + (size_t)i * D_MODEL;
        const float* nw  = norm_w + (size_t)i * D_MODEL;
        const __nv_bfloat16* wih = pWinh  + (size_t)i * D_INNER * D_MODEL;
        const __nv_bfloat16* wil = pWinl  + (size_t)i * D_INNER * D_MODEL;
        const __nv_bfloat16* wrh = pWresh + (size_t)i * D_INNER * D_INNER;
        const __nv_bfloat16* wrl = pWresl + (size_t)i * D_INNER * D_INNER;
        const __nv_bfloat16* woh = pWouth + (size_t)i * D_MODEL * D_INNER;
        const __nv_bfloat16* wol = pWoutl + (size_t)i * D_MODEL * D_INNER;

        rmsnorm_kernel<<<M_ROWS, 256>>>(pX, nw, pXNh, pXNl);

        // in-proj: writes H fp32 + Hh/Hl bf16 split
        hgemm_kernel<3><<<dim3(D_INNER / HBN, M_ROWS / HBM), 256, HG_SMEM>>>(
            pXNh, pXNl, wih, wil, bi, pH, pHh, pHl, M_ROWS, D_INNER, D_MODEL);

        // res-proj + silu
        hgemm_kernel<1><<<dim3(D_INNER / HBN, M_ROWS / HBM), 256, HG_SMEM>>>(
            pHh, pHl, wrh, wrl, br, pRES, nullptr, nullptr, M_ROWS, D_INNER, D_INNER);

        conv_kernel<<<(M_ROWS * D_INNER) / 256, 256>>>(pH, cw, cb, pU);
        bc_kernel<<<M_ROWS / BC_ROWS, 256, BC_SMEM>>>(
            pU, wB, bB, wC, bC, wdt, bdt, pB, pC, pDT);

        scan_kernel<<<dim3(2 * D_INNER / 256, BATCH), 256>>>(
            pU, pRES, pB, pC, pDT, Al, tau, dp, pYRh, pYRl);

        // out-proj: accumulate into residual stream X
        hgemm_kernel<2><<<dim3(D_MODEL / HBN, M_ROWS / HBM), 256, HG_SMEM>>>(
            pYRh, pYRl, woh, wol, bo, pX, nullptr, nullptr, M_ROWS, D_MODEL, D_INNER);
    }

    rmsnorm_kernel<<<M_ROWS, 256>>>(pX, fnw, pXNh, pXNl);

    hgemm_kernel<0><<<dim3(VOCAB / HBN, M_ROWS / HBM), 256, HG_SMEM>>>(
        pXNh, pXNl, pEmbh, pEmbl, nullptr, out, nullptr, nullptr, M_ROWS, VOCAB, D_MODEL);
}

// round 10
// speedup vs baseline: 1.0070x; 1.0070x over previous
#include <cuda_runtime.h>
#include <cuda_bf16.h>
#include <cstdint>
#include <cstddef>

// ---------------- problem constants ----------------
#define D_MODEL 1024
#define N_LAYER 4
#define VOCAB   32000
#define D_STATE 16
#define D_INNER 2048
#define D_CONV  4
#define BATCH   2
#define SEQ     1024
#define M_ROWS  (BATCH * SEQ)     // 2048

// ---------------- scratch (device globals; no allocation allowed) ----------
__device__ float g_X  [M_ROWS * D_MODEL];
__device__ float g_H  [M_ROWS * D_INNER];
__device__ float g_RES[M_ROWS * D_INNER];
__device__ float g_U  [M_ROWS * D_INNER];
__device__ float g_B  [M_ROWS * D_STATE];
__device__ float g_C  [M_ROWS * D_STATE];
__device__ float g_dt [M_ROWS];

// bf16 hi/lo operand buffers
__device__ __nv_bfloat16 g_XNh[M_ROWS * D_MODEL], g_XNl[M_ROWS * D_MODEL];
__device__ __nv_bfloat16 g_Hh [M_ROWS * D_INNER], g_Hl [M_ROWS * D_INNER];
__device__ __nv_bfloat16 g_YRh[M_ROWS * D_INNER], g_YRl[M_ROWS * D_INNER];
__device__ __nv_bfloat16 g_Winh [N_LAYER * D_INNER * D_MODEL], g_Winl [N_LAYER * D_INNER * D_MODEL];
__device__ __nv_bfloat16 g_Wresh[N_LAYER * D_INNER * D_INNER], g_Wresl[N_LAYER * D_INNER * D_INNER];
__device__ __nv_bfloat16 g_Wouth[N_LAYER * D_MODEL * D_INNER], g_Woutl[N_LAYER * D_MODEL * D_INNER];
__device__ __nv_bfloat16 g_Embh [(size_t)VOCAB * D_MODEL],     g_Embl [(size_t)VOCAB * D_MODEL];

// ---------------- small helpers ----------------
__device__ __forceinline__ float silu_f(float x) { return x / (1.f + __expf(-x)); }
__device__ __forceinline__ float softplus_f(float x) { return x > 20.f ? x : log1pf(__expf(x)); }

__device__ __forceinline__ uint32_t smem_addr_u32(const void* p) {
    uint32_t a;
    asm("{ .reg .u64 t; cvta.to.shared.u64 t, %1; cvt.u32.u64 %0, t; }" : "=r"(a) : "l"(p));
    return a;
}
__device__ __forceinline__ void cp16(uint32_t dst, const void* src) {
    asm volatile("cp.async.cg.shared.global [%0], [%1], 16;" :: "r"(dst), "l"(src));
}
__device__ __forceinline__ void cp_commit() {
    asm volatile("cp.async.commit_group;" ::: "memory");
}
template <int N>
__device__ __forceinline__ void cp_wait() {
    asm volatile("cp.async.wait_group %0;" :: "n"(N) : "memory");
}
__device__ __forceinline__ void ldsm4(uint32_t& r0, uint32_t& r1, uint32_t& r2, uint32_t& r3,
                                      uint32_t a) {
    asm volatile("ldmatrix.sync.aligned.m8n8.x4.shared.b16 {%0,%1,%2,%3}, [%4];"
                 : "=r"(r0), "=r"(r1), "=r"(r2), "=r"(r3) : "r"(a));
}
__device__ __forceinline__ void mma_bf16(float& d0, float& d1, float& d2, float& d3,
                                         uint32_t a0, uint32_t a1, uint32_t a2, uint32_t a3,
                                         uint32_t b0, uint32_t b1) {
    asm volatile(
        "mma.sync.aligned.m16n8k16.row.col.f32.bf16.bf16.f32 "
        "{%0,%1,%2,%3}, {%4,%5,%6,%7}, {%8,%9}, {%0,%1,%2,%3};"
        : "+f"(d0), "+f"(d1), "+f"(d2), "+f"(d3)
        : "r"(a0), "r"(a1), "r"(a2), "r"(a3), "r"(b0), "r"(b1));
}
__device__ __forceinline__ void split_bf16(float v, __nv_bfloat16& hi, __nv_bfloat16& lo) {
    hi = __float2bfloat16(v);
    lo = __float2bfloat16(v - __bfloat162float(hi));
}

// ---------------- fp32 -> bf16 hi/lo split (weights) --------------
__global__ void split_kernel(const float4* __restrict__ x,
                             __nv_bfloat162* __restrict__ hi,
                             __nv_bfloat162* __restrict__ lo, int n4) {
    int t = blockIdx.x * 256 + threadIdx.x;
    if (t >= n4) return;
    float4 v = x[t];
    __nv_bfloat16 a = __float2bfloat16(v.x), b = __float2bfloat16(v.y);
    __nv_bfloat16 c = __float2bfloat16(v.z), d = __float2bfloat16(v.w);
    hi[2 * t]     = __nv_bfloat162(a, b);
    hi[2 * t + 1] = __nv_bfloat162(c, d);
    lo[2 * t] = __nv_bfloat162(__float2bfloat16(v.x - __bfloat162float(a)),
                               __float2bfloat16(v.y - __bfloat162float(b)));
    lo[2 * t + 1] = __nv_bfloat162(__float2bfloat16(v.z - __bfloat162float(c)),
                                   __float2bfloat16(v.w - __bfloat162float(d)));
}

// ---------------- embedding gather ----------------
__global__ void embed_kernel(const float* __restrict__ emb,
                             const int* __restrict__ ids,
                             float* __restrict__ X) {
    int t = blockIdx.x * blockDim.x + threadIdx.x;
    int row = t >> 10, col = t & 1023;
    X[t] = emb[(size_t)ids[row] * D_MODEL + col];
}

// ---------------- rmsnorm -> bf16 hi/lo directly ----------------
__global__ void rmsnorm_kernel(const float* __restrict__ X,
                               const float* __restrict__ w,
                               __nv_bfloat16* __restrict__ outh,
                               __nv_bfloat16* __restrict__ outl) {
    int row = blockIdx.x;
    const float* x = X + (size_t)row * D_MODEL;
    float s = 0.f;
    for (int i = threadIdx.x; i < D_MODEL; i += 256) { float v = x[i]; s += v * v; }
    __shared__ float red[256];
    red[threadIdx.x] = s;
    __syncthreads();
    for (int o = 128; o; o >>= 1) {
        if (threadIdx.x < o) red[threadIdx.x] += red[threadIdx.x + o];
        __syncthreads();
    }
    float scale = rsqrtf(red[0] * (1.f / D_MODEL) + 1e-5f);
    for (int i = threadIdx.x; i < D_MODEL; i += 256) {
        float v = x[i] * scale * w[i];
        __nv_bfloat16 hi, lo;
        split_bf16(v, hi, lo);
        outh[(size_t)row * D_MODEL + i] = hi;
        outl[(size_t)row * D_MODEL + i] = lo;
    }
}

// ---------------- depthwise causal conv + silu ----------------
__global__ void conv_kernel(const float* __restrict__ H,
                            const float* __restrict__ cw,
                            const float* __restrict__ cb,
                            float* __restrict__ Uo) {
    int t = blockIdx.x * blockDim.x + threadIdx.x;
    int d = t & (D_INNER - 1);
    int bl = t >> 11;
    int l = bl & (SEQ - 1);
    float acc = cb[d];
#pragma unroll
    for (int j = 0; j < D_CONV; j++) {
        int ll = l - (D_CONV - 1) + j;
        if (ll >= 0)
            acc += H[(size_t)(bl - l + ll) * D_INNER + d] * cw[d * D_CONV + j];
    }
    Uo[t] = silu_f(acc);
}

// ---------------- B, C, dt projections: 8 rows per CTA ----------------
#define BC_ROWS 8
#define BC_SMEM (BC_ROWS * D_INNER * 4)   // 65536 B

__global__ void __launch_bounds__(256) bc_kernel(
    const float* __restrict__ U,
    const float* __restrict__ wB, const float* __restrict__ bB,
    const float* __restrict__ wC, const float* __restrict__ bC,
    const float* __restrict__ wdt, const float* __restrict__ bdt,
    float* __restrict__ Bm, float* __restrict__ Cm,
    float* __restrict__ dtb) {
    extern __shared__ float su[];             // [BC_ROWS][D_INNER]
    int row0 = blockIdx.x * BC_ROWS;
    int tid = threadIdx.x;
    const float4* Uv = (const float4*)(U + (size_t)row0 * D_INNER);
    float4* sv = (float4*)su;
    for (int i = tid; i < BC_ROWS * D_INNER / 4; i += 256)
        sv[i] = Uv[i];
    __syncthreads();
    int warp = tid >> 5, lane = tid & 31;
    for (int j = warp; j < 2 * D_STATE + 1; j += 8) {
        const float* w = (j < D_STATE) ? wB + (size_t)j * D_INNER
                       : (j < 2 * D_STATE) ? wC + (size_t)(j - D_STATE) * D_INNER
                       : wdt;
        float acc[BC_ROWS];
#pragma unroll
        for (int r = 0; r < BC_ROWS; r++) acc[r] = 0.f;
        for (int k = lane; k < D_INNER; k += 32) {
            float wv = w[k];
#pragma unroll
            for (int r = 0; r < BC_ROWS; r++)
                acc[r] += su[r * D_INNER + k] * wv;
        }
#pragma unroll
        for (int r = 0; r < BC_ROWS; r++) {
#pragma unroll
            for (int o = 16; o; o >>= 1)
                acc[r] += __shfl_down_sync(0xffffffffu, acc[r], o);
        }
        if (lane == 0) {
#pragma unroll
            for (int r = 0; r < BC_ROWS; r++) {
                int bl = row0 + r;
                if (j < D_STATE)          Bm[bl * D_STATE + j] = acc[r] + bB[j];
                else if (j < 2 * D_STATE) Cm[bl * D_STATE + (j - D_STATE)] = acc[r] + bC[j - D_STATE];
                else                      dtb[bl] = acc[r] + bdt[0];
            }
        }
    }
}

// ---------------- selective scan: 2 threads per d, writes bf16 hi/lo ----
__global__ void scan_kernel(const float* __restrict__ U,
                            const float* __restrict__ RES,
                            const float* __restrict__ Bm,
                            const float* __restrict__ Cm,
                            const float* __restrict__ dtb,
                            const float* __restrict__ A_log,
                            const float* __restrict__ tau,
                            const float* __restrict__ Dp,
                            __nv_bfloat16* __restrict__ YRh,
                            __nv_bfloat16* __restrict__ YRl) {
    int td = blockIdx.x * 256 + threadIdx.x;   // 0 .. 2*D_INNER-1
    int d = td >> 1;
    int half = td & 1;
    int b = blockIdx.y;

    float a[8], h[8];
#pragma unroll
    for (int n = 0; n < 8; n++) {
        a[n] = -__expf(A_log[(size_t)d * D_STATE + half * 8 + n]);
        h[n] = 0.f;
    }
    float tau_d = tau[d], dpv = Dp[d];
    size_t rowbase = (size_t)b * SEQ;

    for (int l = 0; l < SEQ; l++) {
        size_t bl = rowbase + l;
        float delta = softplus_f(tau_d + dtb[bl]);
        float u = U[bl * D_INNER + d];
        float du = delta * u;
        const float* Bp = Bm + bl * D_STATE + half * 8;
        const float* Cp = Cm + bl * D_STATE + half * 8;
        float y0 = 0.f, y1 = 0.f;
#pragma unroll
        for (int n = 0; n < 8; n++) {
            float da = __expf(delta * a[n]);
            h[n] = da * h[n] + du * Bp[n];
            float yy = Cp[n] * h[n];
            if (n & 1) y1 += yy; else y0 += yy;
        }
        float y = y0 + y1;
        y += __shfl_xor_sync(0xffffffffu, y, 1);
        if (half == 0) {
            float v = (y + dpv * u) * RES[bl * D_INNER + d];
            __nv_bfloat16 hi, lo;
            split_bf16(v, hi, lo);
            YRh[bl * D_INNER + d] = hi;
            YRl[bl * D_INNER + d] = lo;
        }
    }
}

// ---------------- bf16x3 HMMA GEMM: C = A*W^T (+bias, epilogue) ---------
// CTA 128x128x32, 8 warps (4m x 2n), warp tile 32x64 via m16n8k16.
// (R8 inner-loop structure: inline LDSM per p-group; ptxas schedules.)
// EPI: 0 store fp32, 1 silu fp32, 2 accumulate fp32, 3 fp32 + bf16 hi/lo
#define HBM 128
#define HBN 128
#define HBK 32
#define HSTR 40                      // halves per smem row (32 + 8 pad) = 80B
#define A_TILE (HBM * HSTR)          // 5120 halves
#define W_TILE (HBN * HSTR)          // 5120 halves
#define OFF_AH 0
#define OFF_AL (2 * A_TILE)
#define OFF_WH (4 * A_TILE)
#define OFF_WL (4 * A_TILE + 2 * W_TILE)
#define HG_SMEM ((4 * A_TILE + 4 * W_TILE) * 2)   // 81920 B

__device__ __forceinline__ void hfill(const __nv_bfloat16* __restrict__ Ah,
                                      const __nv_bfloat16* __restrict__ Al,
                                      const __nv_bfloat16* __restrict__ Wh,
                                      const __nv_bfloat16* __restrict__ Wl,
                                      int m0, int n0, int K, int k0,
                                      uint32_t smem_u, int stage, int tid) {
    uint32_t baseAh = smem_u + (OFF_AH + stage * A_TILE) * 2;
    uint32_t baseAl = smem_u + (OFF_AL + stage * A_TILE) * 2;
    uint32_t baseWh = smem_u + (OFF_WH + stage * W_TILE) * 2;
    uint32_t baseWl = smem_u + (OFF_WL + stage * W_TILE) * 2;
#pragma unroll
    for (int t = 0; t < 2; t++) {
        int idx = tid + t * 256;            // 0..511 : 128 rows x 4 chunks of 8 halves
        int r = idx >> 2, c = idx & 3;
        size_t go = (size_t)(m0 + r) * K + k0 + c * 8;
        uint32_t so = (uint32_t)(r * HSTR + c * 8) * 2;
        cp16(baseAh + so, Ah + go);
        cp16(baseAl + so, Al + go);
    }
#pragma unroll
    for (int t = 0; t < 2; t++) {
        int idx = tid + t * 256;            // 0..511 : 128 rows x 4 chunks
        int r = idx >> 2, c = idx & 3;
        size_t go = (size_t)(n0 + r) * K + k0 + c * 8;
        uint32_t so = (uint32_t)(r * HSTR + c * 8) * 2;
        cp16(baseWh + so, Wh + go);
        cp16(baseWl + so, Wl + go);
    }
}

template <int EPI>
__global__ void __launch_bounds__(256, 2) hgemm_kernel(
    const __nv_bfloat16* __restrict__ Ah, const __nv_bfloat16* __restrict__ Al,
    const __nv_bfloat16* __restrict__ Wh, const __nv_bfloat16* __restrict__ Wl,
    const float* __restrict__ bias, float* __restrict__ C,
    __nv_bfloat16* __restrict__ Chi, __nv_bfloat16* __restrict__ Clo,
    int M, int N, int K) {
    extern __shared__ __nv_bfloat16 hsm[];
    const uint32_t smem_u = smem_addr_u32(hsm);

    const int tid = threadIdx.x;
    const int wid = tid >> 5;
    const int lane = tid & 31;
    const int wm = wid & 3;       // 0..3: 32 m-rows each
    const int wn = wid >> 2;      // 0..1: 64 n-cols each
    const int m0 = blockIdx.y * HBM;
    const int n0 = blockIdx.x * HBN;

    const int arow = wm * 32 + (lane & 15);
    const int acol = (lane >> 4) * 8;
    const int brow = wn * 64 + (lane & 7) + ((lane >> 4) << 3);
    const int bcol = ((lane >> 3) & 1) * 8;

    float acc[2][8][4];
#pragma unroll
    for (int i = 0; i < 2; i++)
#pragma unroll
        for (int j = 0; j < 8; j++)
#pragma unroll
            for (int v = 0; v < 4; v++) acc[i][j][v] = 0.f;

    const int nb = K / HBK;
    hfill(Ah, Al, Wh, Wl, m0, n0, K, 0, smem_u, 0, tid);
    cp_commit();

    int buf = 0;
    for (int kb = 0; kb < nb; kb++) {
        if (kb + 1 < nb) {
            hfill(Ah, Al, Wh, Wl, m0, n0, K, (kb + 1) * HBK, smem_u, buf ^ 1, tid);
            cp_commit();
            cp_wait<1>();
        } else {
            cp_wait<0>();
        }
        __syncthreads();

        const uint32_t bAh = smem_u + (OFF_AH + buf * A_TILE) * 2;
        const uint32_t bAl = smem_u + (OFF_AL + buf * A_TILE) * 2;
        const uint32_t bWh = smem_u + (OFF_WH + buf * W_TILE) * 2;
        const uint32_t bWl = smem_u + (OFF_WL + buf * W_TILE) * 2;

#pragma unroll
        for (int kk = 0; kk < HBK; kk += 16) {
            uint32_t fah[2][4], fal[2][4];
#pragma unroll
            for (int mt = 0; mt < 2; mt++) {
                uint32_t off = (uint32_t)((arow + mt * 16) * HSTR + kk + acol) * 2;
                ldsm4(fah[mt][0], fah[mt][1], fah[mt][2], fah[mt][3], bAh + off);
                ldsm4(fal[mt][0], fal[mt][1], fal[mt][2], fal[mt][3], bAl + off);
            }
#pragma unroll
            for (int p = 0; p < 4; p++) {      // 4 groups of 16 n-rows
                uint32_t bh[4], bl_[4];
                uint32_t off = (uint32_t)((brow + p * 16) * HSTR + kk + bcol) * 2;
                ldsm4(bh[0], bh[1], bh[2], bh[3], bWh + off);
                ldsm4(bl_[0], bl_[1], bl_[2], bl_[3], bWl + off);
#pragma unroll
                for (int mt = 0; mt < 2; mt++) {
                    float* d0 = acc[mt][p * 2];
                    float* d1 = acc[mt][p * 2 + 1];
                    mma_bf16(d0[0], d0[1], d0[2], d0[3],
                             fah[mt][0], fah[mt][1], fah[mt][2], fah[mt][3], bh[0], bh[1]);
                    mma_bf16(d0[0], d0[1], d0[2], d0[3],
                             fal[mt][0], fal[mt][1], fal[mt][2], fal[mt][3], bh[0], bh[1]);
                    mma_bf16(d0[0], d0[1], d0[2], d0[3],
                             fah[mt][0], fah[mt][1], fah[mt][2], fah[mt][3], bl_[0], bl_[1]);
                    mma_bf16(d1[0], d1[1], d1[2], d1[3],
                             fah[mt][0], fah[mt][1], fah[mt][2], fah[mt][3], bh[2], bh[3]);
                    mma_bf16(d1[0], d1[1], d1[2], d1[3],
                             fal[mt][0], fal[mt][1], fal[mt][2], fal[mt][3], bh[2], bh[3]);
                    mma_bf16(d1[0], d1[1], d1[2], d1[3],
                             fah[mt][0], fah[mt][1], fah[mt][2], fah[mt][3], bl_[2], bl_[3]);
                }
            }
        }
        __syncthreads();
        buf ^= 1;
    }

    // ---- epilogue ----
    const int g = lane >> 2, tg = lane & 3;
#pragma unroll
    for (int mt = 0; mt < 2; mt++) {
#pragma unroll
        for (int nt = 0; nt < 8; nt++) {
            int m = m0 + wm * 32 + mt * 16 + g;
            int n = n0 + wn * 64 + nt * 8 + tg * 2;
            float b0 = bias ? bias[n] : 0.f;
            float b1 = bias ? bias[n + 1] : 0.f;
#pragma unroll
            for (int half = 0; half < 2; half++) {
                int mm = m + half * 8;
                float v0 = acc[mt][nt][half * 2 + 0] + b0;
                float v1 = acc[mt][nt][half * 2 + 1] + b1;
                if (EPI == 1) { v0 = silu_f(v0); v1 = silu_f(v1); }
                size_t off = (size_t)mm * N + n;
                if (EPI == 2) { C[off] += v0; C[off + 1] += v1; }
                else          { C[off] = v0;  C[off + 1] = v1; }
                if (EPI == 3) {
                    __nv_bfloat16 h0, l0, h1, l1;
                    split_bf16(v0, h0, l0);
                    split_bf16(v1, h1, l1);
                    Chi[off] = h0; Chi[off + 1] = h1;
                    Clo[off] = l0; Clo[off + 1] = l1;
                }
            }
        }
    }
}

// ---------------- launch ----------------
static inline void split_launch(const float* src, __nv_bfloat16* hi, __nv_bfloat16* lo, size_t n) {
    int n4 = (int)(n / 4);
    split_kernel<<<(n4 + 255) / 256, 256>>>((const float4*)src, (__nv_bfloat162*)hi,
                                            (__nv_bfloat162*)lo, n4);
}

extern "C" void kernel_launch(void* const* d_in, const int* in_sizes, int n_in,
                              void* d_out, int out_size) {
    const float* emb    = (const float*)d_in[0];
    const float* norm_w = (const float*)d_in[1];
    const float* w_in   = (const float*)d_in[2];
    const float* b_in   = (const float*)d_in[3];
    const float* w_res  = (const float*)d_in[4];
    const float* b_res  = (const float*)d_in[5];
    const float* conv_w = (const float*)d_in[6];
    const float* conv_b = (const float*)d_in[7];
    const float* w_B    = (const float*)d_in[8];
    const float* b_B    = (const float*)d_in[9];
    const float* w_C    = (const float*)d_in[10];
    const float* b_C    = (const float*)d_in[11];
    const float* w_dt   = (const float*)d_in[12];
    const float* b_dt   = (const float*)d_in[13];
    const float* tau_dt = (const float*)d_in[14];
    const float* A_log  = (const float*)d_in[15];
    const float* Dp     = (const float*)d_in[16];
    const float* w_out  = (const float*)d_in[17];
    const float* b_out  = (const float*)d_in[18];
    const float* fnw    = (const float*)d_in[19];
    const int*   ids    = (const int*)d_in[20];
    float* out = (float*)d_out;

    cudaFuncSetAttribute(hgemm_kernel<0>, cudaFuncAttributeMaxDynamicSharedMemorySize, HG_SMEM);
    cudaFuncSetAttribute(hgemm_kernel<1>, cudaFuncAttributeMaxDynamicSharedMemorySize, HG_SMEM);
    cudaFuncSetAttribute(hgemm_kernel<2>, cudaFuncAttributeMaxDynamicSharedMemorySize, HG_SMEM);
    cudaFuncSetAttribute(hgemm_kernel<3>, cudaFuncAttributeMaxDynamicSharedMemorySize, HG_SMEM);
    cudaFuncSetAttribute(bc_kernel, cudaFuncAttributeMaxDynamicSharedMemorySize, BC_SMEM);

    float *pX, *pH, *pRES, *pU, *pB, *pC, *pDT;
    cudaGetSymbolAddress((void**)&pX, g_X);
    cudaGetSymbolAddress((void**)&pH, g_H);
    cudaGetSymbolAddress((void**)&pRES, g_RES);
    cudaGetSymbolAddress((void**)&pU, g_U);
    cudaGetSymbolAddress((void**)&pB, g_B);
    cudaGetSymbolAddress((void**)&pC, g_C);
    cudaGetSymbolAddress((void**)&pDT, g_dt);

    __nv_bfloat16 *pXNh, *pXNl, *pHh, *pHl, *pYRh, *pYRl;
    __nv_bfloat16 *pWinh, *pWinl, *pWresh, *pWresl, *pWouth, *pWoutl, *pEmbh, *pEmbl;
    cudaGetSymbolAddress((void**)&pXNh, g_XNh);  cudaGetSymbolAddress((void**)&pXNl, g_XNl);
    cudaGetSymbolAddress((void**)&pHh, g_Hh);    cudaGetSymbolAddress((void**)&pHl, g_Hl);
    cudaGetSymbolAddress((void**)&pYRh, g_YRh);  cudaGetSymbolAddress((void**)&pYRl, g_YRl);
    cudaGetSymbolAddress((void**)&pWinh, g_Winh);   cudaGetSymbolAddress((void**)&pWinl, g_Winl);
    cudaGetSymbolAddress((void**)&pWresh, g_Wresh); cudaGetSymbolAddress((void**)&pWresl, g_Wresl);
    cudaGetSymbolAddress((void**)&pWouth, g_Wouth); cudaGetSymbolAddress((void**)&pWoutl, g_Woutl);
    cudaGetSymbolAddress((void**)&pEmbh, g_Embh);   cudaGetSymbolAddress((void**)&pEmbl, g_Embl);

    // weight conversions (all layers at once)
    split_launch(emb,   pEmbh,  pEmbl,  (size_t)VOCAB * D_MODEL);
    split_launch(w_in,  pWinh,  pWinl,  (size_t)N_LAYER * D_INNER * D_MODEL);
    split_launch(w_res, pWresh, pWresl, (size_t)N_LAYER * D_INNER * D_INNER);
    split_launch(w_out, pWouth, pWoutl, (size_t)N_LAYER * D_MODEL * D_INNER);

    embed_kernel<<<(M_ROWS * D_MODEL) / 256, 256>>>(emb, ids, pX);

    for (int i = 0; i < N_LAYER; i++) {
        const float* bi  = b_in   + (size_t)i * D_INNER;
        const float* br  = b_res  + (size_t)i * D_INNER;
        const float* cw  = conv_w + (size_t)i * D_INNER * D_CONV;
        const float* cb  = conv_b + (size_t)i * D_INNER;
        const float* wB  = w_B  + (size_t)i * D_STATE * D_INNER;
        const float* bB  = b_B  + (size_t)i * D_STATE;
        const float* wC  = w_C  + (size_t)i * D_STATE * D_INNER;
        const float* bC  = b_C  + (size_t)i * D_STATE;
        const float* wdt = w_dt + (size_t)i * D_INNER;
        const float* bdt = b_dt + (size_t)i;
        const float* tau = tau_dt + (size_t)i * D_INNER;
        const float* Al  = A_log + (size_t)i * D_INNER * D_STATE;
        const float* dp  = Dp    + (size_t)i * D_INNER;
        const float* bo  = b_out + (size_t)i * D_MODEL;
        const float* nw  = norm_w + (size_t)i * D_MODEL;
        const __nv_bfloat16* wih = pWinh  + (size_t)i * D_INNER * D_MODEL;
        const __nv_bfloat16* wil = pWinl  + (size_t)i * D_INNER * D_MODEL;
        const __nv_bfloat16* wrh = pWresh + (size_t)i * D_INNER * D_INNER;
        const __nv_bfloat16* wrl = pWresl + (size_t)i * D_INNER * D_INNER;
        const __nv_bfloat16* woh = pWouth + (size_t)i * D_MODEL * D_INNER;
        const __nv_bfloat16* wol = pWoutl + (size_t)i * D_MODEL * D_INNER;

        rmsnorm_kernel<<<M_ROWS, 256>>>(pX, nw, pXNh, pXNl);

        // in-proj: writes H fp32 + Hh/Hl bf16 split
        hgemm_kernel<3><<<dim3(D_INNER / HBN, M_ROWS / HBM), 256, HG_SMEM>>>(
            pXNh, pXNl, wih, wil, bi, pH, pHh, pHl, M_ROWS, D_INNER, D_MODEL);

        // res-proj + silu
        hgemm_kernel<1><<<dim3(D_INNER / HBN, M_ROWS / HBM), 256, HG_SMEM>>>(
            pHh, pHl, wrh, wrl, br, pRES, nullptr, nullptr, M_ROWS, D_INNER, D_INNER);

        conv_kernel<<<(M_ROWS * D_INNER) / 256, 256>>>(pH, cw, cb, pU);
        bc_kernel<<<M_ROWS / BC_ROWS, 256, BC_SMEM>>>(
            pU, wB, bB, wC, bC, wdt, bdt, pB, pC, pDT);

        scan_kernel<<<dim3(2 * D_INNER / 256, BATCH), 256>>>(
            pU, pRES, pB, pC, pDT, Al, tau, dp, pYRh, pYRl);

        // out-proj: accumulate into residual stream X
        hgemm_kernel<2><<<dim3(D_MODEL / HBN, M_ROWS / HBM), 256, HG_SMEM>>>(
            pYRh, pYRl, woh, wol, bo, pX, nullptr, nullptr, M_ROWS, D_MODEL, D_INNER);
    }

    rmsnorm_kernel<<<M_ROWS, 256>>>(pX, fnw, pXNh, pXNl);

    hgemm_kernel<0><<<dim3(VOCAB / HBN, M_ROWS / HBM), 256, HG_SMEM>>>(
        pXNh, pXNl, pEmbh, pEmbl, nullptr, out, nullptr, nullptr, M_ROWS, VOCAB, D_MODEL);
}

// round 11
// speedup vs baseline: 1.0556x; 1.0482x over previous
#include <cuda_runtime.h>
#include <cuda_bf16.h>
#include <cstdint>
#include <cstddef>

// ---------------- problem constants ----------------
#define D_MODEL 1024
#define N_LAYER 4
#define VOCAB   32000
#define D_STATE 16
#define D_INNER 2048
#define D_CONV  4
#define BATCH   2
#define SEQ     1024
#define M_ROWS  (BATCH * SEQ)     // 2048

// ---------------- scratch (device globals; no allocation allowed) ----------
__device__ float g_X  [M_ROWS * D_MODEL];
__device__ float g_H  [M_ROWS * D_INNER];
__device__ float g_RES[M_ROWS * D_INNER];
__device__ float g_U  [M_ROWS * D_INNER];
__device__ float g_B  [M_ROWS * D_STATE];
__device__ float g_C  [M_ROWS * D_STATE];
__device__ float g_dt [M_ROWS];

// bf16 hi/lo operand buffers
__device__ __nv_bfloat16 g_XNh[M_ROWS * D_MODEL], g_XNl[M_ROWS * D_MODEL];
__device__ __nv_bfloat16 g_Hh [M_ROWS * D_INNER], g_Hl [M_ROWS * D_INNER];
__device__ __nv_bfloat16 g_YRh[M_ROWS * D_INNER], g_YRl[M_ROWS * D_INNER];
__device__ __nv_bfloat16 g_Winh [N_LAYER * D_INNER * D_MODEL], g_Winl [N_LAYER * D_INNER * D_MODEL];
__device__ __nv_bfloat16 g_Wresh[N_LAYER * D_INNER * D_INNER], g_Wresl[N_LAYER * D_INNER * D_INNER];
__device__ __nv_bfloat16 g_Wouth[N_LAYER * D_MODEL * D_INNER], g_Woutl[N_LAYER * D_MODEL * D_INNER];
__device__ __nv_bfloat16 g_Embh [(size_t)VOCAB * D_MODEL],     g_Embl [(size_t)VOCAB * D_MODEL];

// ---------------- small helpers ----------------
__device__ __forceinline__ float silu_f(float x) { return x / (1.f + __expf(-x)); }
__device__ __forceinline__ float softplus_f(float x) { return x > 20.f ? x : log1pf(__expf(x)); }

__device__ __forceinline__ uint32_t smem_addr_u32(const void* p) {
    uint32_t a;
    asm("{ .reg .u64 t; cvta.to.shared.u64 t, %1; cvt.u32.u64 %0, t; }" : "=r"(a) : "l"(p));
    return a;
}
__device__ __forceinline__ void cp16(uint32_t dst, const void* src) {
    asm volatile("cp.async.cg.shared.global [%0], [%1], 16;" :: "r"(dst), "l"(src));
}
__device__ __forceinline__ void cp_commit() {
    asm volatile("cp.async.commit_group;" ::: "memory");
}
template <int N>
__device__ __forceinline__ void cp_wait() {
    asm volatile("cp.async.wait_group %0;" :: "n"(N) : "memory");
}
__device__ __forceinline__ void ldsm4(uint32_t& r0, uint32_t& r1, uint32_t& r2, uint32_t& r3,
                                      uint32_t a) {
    asm volatile("ldmatrix.sync.aligned.m8n8.x4.shared.b16 {%0,%1,%2,%3}, [%4];"
                 : "=r"(r0), "=r"(r1), "=r"(r2), "=r"(r3) : "r"(a));
}
__device__ __forceinline__ void mma_bf16(float& d0, float& d1, float& d2, float& d3,
                                         uint32_t a0, uint32_t a1, uint32_t a2, uint32_t a3,
                                         uint32_t b0, uint32_t b1) {
    asm volatile(
        "mma.sync.aligned.m16n8k16.row.col.f32.bf16.bf16.f32 "
        "{%0,%1,%2,%3}, {%4,%5,%6,%7}, {%8,%9}, {%0,%1,%2,%3};"
        : "+f"(d0), "+f"(d1), "+f"(d2), "+f"(d3)
        : "r"(a0), "r"(a1), "r"(a2), "r"(a3), "r"(b0), "r"(b1));
}
__device__ __forceinline__ void split_bf16(float v, __nv_bfloat16& hi, __nv_bfloat16& lo) {
    hi = __float2bfloat16(v);
    lo = __float2bfloat16(v - __bfloat162float(hi));
}

// ---------------- fp32 -> bf16 hi/lo split (weights) --------------
__global__ void split_kernel(const float4* __restrict__ x,
                             __nv_bfloat162* __restrict__ hi,
                             __nv_bfloat162* __restrict__ lo, int n4) {
    int t = blockIdx.x * 256 + threadIdx.x;
    if (t >= n4) return;
    float4 v = x[t];
    __nv_bfloat16 a = __float2bfloat16(v.x), b = __float2bfloat16(v.y);
    __nv_bfloat16 c = __float2bfloat16(v.z), d = __float2bfloat16(v.w);
    hi[2 * t]     = __nv_bfloat162(a, b);
    hi[2 * t + 1] = __nv_bfloat162(c, d);
    lo[2 * t] = __nv_bfloat162(__float2bfloat16(v.x - __bfloat162float(a)),
                               __float2bfloat16(v.y - __bfloat162float(b)));
    lo[2 * t + 1] = __nv_bfloat162(__float2bfloat16(v.z - __bfloat162float(c)),
                                   __float2bfloat16(v.w - __bfloat162float(d)));
}

// ---------------- embedding gather ----------------
__global__ void embed_kernel(const float* __restrict__ emb,
                             const int* __restrict__ ids,
                             float* __restrict__ X) {
    int t = blockIdx.x * blockDim.x + threadIdx.x;
    int row = t >> 10, col = t & 1023;
    X[t] = emb[(size_t)ids[row] * D_MODEL + col];
}

// ---------------- rmsnorm -> bf16 hi/lo directly ----------------
__global__ void rmsnorm_kernel(const float* __restrict__ X,
                               const float* __restrict__ w,
                               __nv_bfloat16* __restrict__ outh,
                               __nv_bfloat16* __restrict__ outl) {
    int row = blockIdx.x;
    const float* x = X + (size_t)row * D_MODEL;
    float s = 0.f;
    for (int i = threadIdx.x; i < D_MODEL; i += 256) { float v = x[i]; s += v * v; }
    __shared__ float red[256];
    red[threadIdx.x] = s;
    __syncthreads();
    for (int o = 128; o; o >>= 1) {
        if (threadIdx.x < o) red[threadIdx.x] += red[threadIdx.x + o];
        __syncthreads();
    }
    float scale = rsqrtf(red[0] * (1.f / D_MODEL) + 1e-5f);
    for (int i = threadIdx.x; i < D_MODEL; i += 256) {
        float v = x[i] * scale * w[i];
        __nv_bfloat16 hi, lo;
        split_bf16(v, hi, lo);
        outh[(size_t)row * D_MODEL + i] = hi;
        outl[(size_t)row * D_MODEL + i] = lo;
    }
}

// ---------------- depthwise causal conv + silu ----------------
__global__ void conv_kernel(const float* __restrict__ H,
                            const float* __restrict__ cw,
                            const float* __restrict__ cb,
                            float* __restrict__ Uo) {
    int t = blockIdx.x * blockDim.x + threadIdx.x;
    int d = t & (D_INNER - 1);
    int bl = t >> 11;
    int l = bl & (SEQ - 1);
    float acc = cb[d];
#pragma unroll
    for (int j = 0; j < D_CONV; j++) {
        int ll = l - (D_CONV - 1) + j;
        if (ll >= 0)
            acc += H[(size_t)(bl - l + ll) * D_INNER + d] * cw[d * D_CONV + j];
    }
    Uo[t] = silu_f(acc);
}

// ---------------- B, C, dt projections (R8 simple version) ----------------
__global__ void bc_kernel(const float* __restrict__ U,
                          const float* __restrict__ wB, const float* __restrict__ bB,
                          const float* __restrict__ wC, const float* __restrict__ bC,
                          const float* __restrict__ wdt, const float* __restrict__ bdt,
                          float* __restrict__ Bm, float* __restrict__ Cm,
                          float* __restrict__ dtb) {
    int bl = blockIdx.x;
    __shared__ float su[D_INNER];
    const float* u = U + (size_t)bl * D_INNER;
    for (int i = threadIdx.x; i < D_INNER; i += 256) su[i] = u[i];
    __syncthreads();
    int warp = threadIdx.x >> 5, lane = threadIdx.x & 31;
    for (int j = warp; j < 2 * D_STATE + 1; j += 8) {
        const float* w = (j < D_STATE) ? wB + (size_t)j * D_INNER
                       : (j < 2 * D_STATE) ? wC + (size_t)(j - D_STATE) * D_INNER
                       : wdt;
        float s = 0.f;
        for (int i = lane; i < D_INNER; i += 32) s += su[i] * w[i];
#pragma unroll
        for (int o = 16; o; o >>= 1) s += __shfl_down_sync(0xffffffffu, s, o);
        if (lane == 0) {
            if (j < D_STATE)          Bm[bl * D_STATE + j] = s + bB[j];
            else if (j < 2 * D_STATE) Cm[bl * D_STATE + (j - D_STATE)] = s + bC[j - D_STATE];
            else                      dtb[bl] = s + bdt[0];
        }
    }
}

// ---------------- selective scan: 2 threads per d, writes bf16 hi/lo ----
__global__ void scan_kernel(const float* __restrict__ U,
                            const float* __restrict__ RES,
                            const float* __restrict__ Bm,
                            const float* __restrict__ Cm,
                            const float* __restrict__ dtb,
                            const float* __restrict__ A_log,
                            const float* __restrict__ tau,
                            const float* __restrict__ Dp,
                            __nv_bfloat16* __restrict__ YRh,
                            __nv_bfloat16* __restrict__ YRl) {
    int td = blockIdx.x * 256 + threadIdx.x;   // 0 .. 2*D_INNER-1
    int d = td >> 1;
    int half = td & 1;
    int b = blockIdx.y;

    float a[8], h[8];
#pragma unroll
    for (int n = 0; n < 8; n++) {
        a[n] = -__expf(A_log[(size_t)d * D_STATE + half * 8 + n]);
        h[n] = 0.f;
    }
    float tau_d = tau[d], dpv = Dp[d];
    size_t rowbase = (size_t)b * SEQ;

    for (int l = 0; l < SEQ; l++) {
        size_t bl = rowbase + l;
        float delta = softplus_f(tau_d + dtb[bl]);
        float u = U[bl * D_INNER + d];
        float du = delta * u;
        const float* Bp = Bm + bl * D_STATE + half * 8;
        const float* Cp = Cm + bl * D_STATE + half * 8;
        float y0 = 0.f, y1 = 0.f;
#pragma unroll
        for (int n = 0; n < 8; n++) {
            float da = __expf(delta * a[n]);
            h[n] = da * h[n] + du * Bp[n];
            float yy = Cp[n] * h[n];
            if (n & 1) y1 += yy; else y0 += yy;
        }
        float y = y0 + y1;
        y += __shfl_xor_sync(0xffffffffu, y, 1);
        if (half == 0) {
            float v = (y + dpv * u) * RES[bl * D_INNER + d];
            __nv_bfloat16 hi, lo;
            split_bf16(v, hi, lo);
            YRh[bl * D_INNER + d] = hi;
            YRl[bl * D_INNER + d] = lo;
        }
    }
}

// ---------------- bf16x3 HMMA GEMM 128x128 (R8): C = A*W^T ---------
// EPI: 0 store fp32, 1 silu fp32, 2 accumulate fp32, 3 fp32 + bf16 hi/lo
#define HBM 128
#define HBN 128
#define HBK 32
#define HSTR 40
#define A_TILE (HBM * HSTR)
#define W_TILE (HBN * HSTR)
#define OFF_AH 0
#define OFF_AL (2 * A_TILE)
#define OFF_WH (4 * A_TILE)
#define OFF_WL (4 * A_TILE + 2 * W_TILE)
#define HG_SMEM ((4 * A_TILE + 4 * W_TILE) * 2)   // 81920 B

__device__ __forceinline__ void hfill(const __nv_bfloat16* __restrict__ Ah,
                                      const __nv_bfloat16* __restrict__ Al,
                                      const __nv_bfloat16* __restrict__ Wh,
                                      const __nv_bfloat16* __restrict__ Wl,
                                      int m0, int n0, int K, int k0,
                                      uint32_t smem_u, int stage, int tid) {
    uint32_t baseAh = smem_u + (OFF_AH + stage * A_TILE) * 2;
    uint32_t baseAl = smem_u + (OFF_AL + stage * A_TILE) * 2;
    uint32_t baseWh = smem_u + (OFF_WH + stage * W_TILE) * 2;
    uint32_t baseWl = smem_u + (OFF_WL + stage * W_TILE) * 2;
#pragma unroll
    for (int t = 0; t < 2; t++) {
        int idx = tid + t * 256;
        int r = idx >> 2, c = idx & 3;
        size_t go = (size_t)(m0 + r) * K + k0 + c * 8;
        uint32_t so = (uint32_t)(r * HSTR + c * 8) * 2;
        cp16(baseAh + so, Ah + go);
        cp16(baseAl + so, Al + go);
    }
#pragma unroll
    for (int t = 0; t < 2; t++) {
        int idx = tid + t * 256;
        int r = idx >> 2, c = idx & 3;
        size_t go = (size_t)(n0 + r) * K + k0 + c * 8;
        uint32_t so = (uint32_t)(r * HSTR + c * 8) * 2;
        cp16(baseWh + so, Wh + go);
        cp16(baseWl + so, Wl + go);
    }
}

template <int EPI>
__global__ void __launch_bounds__(256, 2) hgemm_kernel(
    const __nv_bfloat16* __restrict__ Ah, const __nv_bfloat16* __restrict__ Al,
    const __nv_bfloat16* __restrict__ Wh, const __nv_bfloat16* __restrict__ Wl,
    const float* __restrict__ bias, float* __restrict__ C,
    __nv_bfloat16* __restrict__ Chi, __nv_bfloat16* __restrict__ Clo,
    int M, int N, int K) {
    extern __shared__ __nv_bfloat16 hsm[];
    const uint32_t smem_u = smem_addr_u32(hsm);

    const int tid = threadIdx.x;
    const int wid = tid >> 5;
    const int lane = tid & 31;
    const int wm = wid & 3;
    const int wn = wid >> 2;
    const int m0 = blockIdx.y * HBM;
    const int n0 = blockIdx.x * HBN;

    const int arow = wm * 32 + (lane & 15);
    const int acol = (lane >> 4) * 8;
    const int brow = wn * 64 + (lane & 7) + ((lane >> 4) << 3);
    const int bcol = ((lane >> 3) & 1) * 8;

    float acc[2][8][4];
#pragma unroll
    for (int i = 0; i < 2; i++)
#pragma unroll
        for (int j = 0; j < 8; j++)
#pragma unroll
            for (int v = 0; v < 4; v++) acc[i][j][v] = 0.f;

    const int nb = K / HBK;
    hfill(Ah, Al, Wh, Wl, m0, n0, K, 0, smem_u, 0, tid);
    cp_commit();

    int buf = 0;
    for (int kb = 0; kb < nb; kb++) {
        if (kb + 1 < nb) {
            hfill(Ah, Al, Wh, Wl, m0, n0, K, (kb + 1) * HBK, smem_u, buf ^ 1, tid);
            cp_commit();
            cp_wait<1>();
        } else {
            cp_wait<0>();
        }
        __syncthreads();

        const uint32_t bAh = smem_u + (OFF_AH + buf * A_TILE) * 2;
        const uint32_t bAl = smem_u + (OFF_AL + buf * A_TILE) * 2;
        const uint32_t bWh = smem_u + (OFF_WH + buf * W_TILE) * 2;
        const uint32_t bWl = smem_u + (OFF_WL + buf * W_TILE) * 2;

#pragma unroll
        for (int kk = 0; kk < HBK; kk += 16) {
            uint32_t fah[2][4], fal[2][4];
#pragma unroll
            for (int mt = 0; mt < 2; mt++) {
                uint32_t off = (uint32_t)((arow + mt * 16) * HSTR + kk + acol) * 2;
                ldsm4(fah[mt][0], fah[mt][1], fah[mt][2], fah[mt][3], bAh + off);
                ldsm4(fal[mt][0], fal[mt][1], fal[mt][2], fal[mt][3], bAl + off);
            }
#pragma unroll
            for (int p = 0; p < 4; p++) {
                uint32_t bh[4], bl_[4];
                uint32_t off = (uint32_t)((brow + p * 16) * HSTR + kk + bcol) * 2;
                ldsm4(bh[0], bh[1], bh[2], bh[3], bWh + off);
                ldsm4(bl_[0], bl_[1], bl_[2], bl_[3], bWl + off);
#pragma unroll
                for (int mt = 0; mt < 2; mt++) {
                    float* d0 = acc[mt][p * 2];
                    float* d1 = acc[mt][p * 2 + 1];
                    mma_bf16(d0[0], d0[1], d0[2], d0[3],
                             fah[mt][0], fah[mt][1], fah[mt][2], fah[mt][3], bh[0], bh[1]);
                    mma_bf16(d0[0], d0[1], d0[2], d0[3],
                             fal[mt][0], fal[mt][1], fal[mt][2], fal[mt][3], bh[0], bh[1]);
                    mma_bf16(d0[0], d0[1], d0[2], d0[3],
                             fah[mt][0], fah[mt][1], fah[mt][2], fah[mt][3], bl_[0], bl_[1]);
                    mma_bf16(d1[0], d1[1], d1[2], d1[3],
                             fah[mt][0], fah[mt][1], fah[mt][2], fah[mt][3], bh[2], bh[3]);
                    mma_bf16(d1[0], d1[1], d1[2], d1[3],
                             fal[mt][0], fal[mt][1], fal[mt][2], fal[mt][3], bh[2], bh[3]);
                    mma_bf16(d1[0], d1[1], d1[2], d1[3],
                             fah[mt][0], fah[mt][1], fah[mt][2], fah[mt][3], bl_[2], bl_[3]);
                }
            }
        }
        __syncthreads();
        buf ^= 1;
    }

    const int g = lane >> 2, tg = lane & 3;
#pragma unroll
    for (int mt = 0; mt < 2; mt++) {
#pragma unroll
        for (int nt = 0; nt < 8; nt++) {
            int m = m0 + wm * 32 + mt * 16 + g;
            int n = n0 + wn * 64 + nt * 8 + tg * 2;
            float b0 = bias ? bias[n] : 0.f;
            float b1 = bias ? bias[n + 1] : 0.f;
#pragma unroll
            for (int half = 0; half < 2; half++) {
                int mm = m + half * 8;
                float v0 = acc[mt][nt][half * 2 + 0] + b0;
                float v1 = acc[mt][nt][half * 2 + 1] + b1;
                if (EPI == 1) { v0 = silu_f(v0); v1 = silu_f(v1); }
                size_t off = (size_t)mm * N + n;
                if (EPI == 2) { C[off] += v0; C[off + 1] += v1; }
                else          { C[off] = v0;  C[off + 1] = v1; }
                if (EPI == 3) {
                    __nv_bfloat16 h0, l0, h1, l1;
                    split_bf16(v0, h0, l0);
                    split_bf16(v1, h1, l1);
                    Chi[off] = h0; Chi[off + 1] = h1;
                    Clo[off] = l0; Clo[off + 1] = l1;
                }
            }
        }
    }
}

// ---------------- bf16x3 HMMA GEMM 128x64 (R7) — for out-proj ----------
// 8 warps (4m x 2n), warp tile 32x32. Accumulates into C (EPI=2 semantics).
#define G64_BN 64
#define G64_WT (G64_BN * HSTR)      // 2560 halves
#define G64_OFF_AH 0
#define G64_OFF_AL (2 * A_TILE)
#define G64_OFF_WH (4 * A_TILE)
#define G64_OFF_WL (4 * A_TILE + 2 * G64_WT)
#define G64_SMEM ((4 * A_TILE + 4 * G64_WT) * 2)   // 61440 B

__device__ __forceinline__ void hfill64(const __nv_bfloat16* __restrict__ Ah,
                                        const __nv_bfloat16* __restrict__ Al,
                                        const __nv_bfloat16* __restrict__ Wh,
                                        const __nv_bfloat16* __restrict__ Wl,
                                        int m0, int n0, int K, int k0,
                                        uint32_t smem_u, int stage, int tid) {
    uint32_t baseAh = smem_u + (G64_OFF_AH + stage * A_TILE) * 2;
    uint32_t baseAl = smem_u + (G64_OFF_AL + stage * A_TILE) * 2;
    uint32_t baseWh = smem_u + (G64_OFF_WH + stage * G64_WT) * 2;
    uint32_t baseWl = smem_u + (G64_OFF_WL + stage * G64_WT) * 2;
#pragma unroll
    for (int t = 0; t < 2; t++) {
        int idx = tid + t * 256;
        int r = idx >> 2, c = idx & 3;
        size_t go = (size_t)(m0 + r) * K + k0 + c * 8;
        uint32_t so = (uint32_t)(r * HSTR + c * 8) * 2;
        cp16(baseAh + so, Ah + go);
        cp16(baseAl + so, Al + go);
    }
    {
        int r = tid >> 2, c = tid & 3;
        size_t go = (size_t)(n0 + r) * K + k0 + c * 8;
        uint32_t so = (uint32_t)(r * HSTR + c * 8) * 2;
        cp16(baseWh + so, Wh + go);
        cp16(baseWl + so, Wl + go);
    }
}

__global__ void __launch_bounds__(256, 2) hgemm64_acc_kernel(
    const __nv_bfloat16* __restrict__ Ah, const __nv_bfloat16* __restrict__ Al,
    const __nv_bfloat16* __restrict__ Wh, const __nv_bfloat16* __restrict__ Wl,
    const float* __restrict__ bias, float* __restrict__ C,
    int M, int N, int K) {
    extern __shared__ __nv_bfloat16 hsm[];
    const uint32_t smem_u = smem_addr_u32(hsm);

    const int tid = threadIdx.x;
    const int wid = tid >> 5;
    const int lane = tid & 31;
    const int wm = wid & 3;
    const int wn = wid >> 2;
    const int m0 = blockIdx.y * HBM;
    const int n0 = blockIdx.x * G64_BN;

    const int arow = wm * 32 + (lane & 15);
    const int acol = (lane >> 4) * 8;
    const int brow = wn * 32 + (lane & 7) + ((lane >> 4) << 3);
    const int bcol = ((lane >> 3) & 1) * 8;

    float acc[2][4][4];
#pragma unroll
    for (int i = 0; i < 2; i++)
#pragma unroll
        for (int j = 0; j < 4; j++)
#pragma unroll
            for (int v = 0; v < 4; v++) acc[i][j][v] = 0.f;

    const int nb = K / HBK;
    hfill64(Ah, Al, Wh, Wl, m0, n0, K, 0, smem_u, 0, tid);
    cp_commit();

    int buf = 0;
    for (int kb = 0; kb < nb; kb++) {
        if (kb + 1 < nb) {
            hfill64(Ah, Al, Wh, Wl, m0, n0, K, (kb + 1) * HBK, smem_u, buf ^ 1, tid);
            cp_commit();
            cp_wait<1>();
        } else {
            cp_wait<0>();
        }
        __syncthreads();

        const uint32_t bAh = smem_u + (G64_OFF_AH + buf * A_TILE) * 2;
        const uint32_t bAl = smem_u + (G64_OFF_AL + buf * A_TILE) * 2;
        const uint32_t bWh = smem_u + (G64_OFF_WH + buf * G64_WT) * 2;
        const uint32_t bWl = smem_u + (G64_OFF_WL + buf * G64_WT) * 2;

#pragma unroll
        for (int kk = 0; kk < HBK; kk += 16) {
            uint32_t fah[2][4], fal[2][4], fbh[2][4], fbl[2][4];
#pragma unroll
            for (int mt = 0; mt < 2; mt++) {
                uint32_t off = (uint32_t)((arow + mt * 16) * HSTR + kk + acol) * 2;
                ldsm4(fah[mt][0], fah[mt][1], fah[mt][2], fah[mt][3], bAh + off);
                ldsm4(fal[mt][0], fal[mt][1], fal[mt][2], fal[mt][3], bAl + off);
            }
#pragma unroll
            for (int p = 0; p < 2; p++) {
                uint32_t off = (uint32_t)((brow + p * 16) * HSTR + kk + bcol) * 2;
                ldsm4(fbh[p][0], fbh[p][1], fbh[p][2], fbh[p][3], bWh + off);
                ldsm4(fbl[p][0], fbl[p][1], fbl[p][2], fbl[p][3], bWl + off);
            }
#pragma unroll
            for (int mt = 0; mt < 2; mt++) {
#pragma unroll
                for (int p = 0; p < 2; p++) {
                    float* d0 = acc[mt][p * 2];
                    float* d1 = acc[mt][p * 2 + 1];
                    mma_bf16(d0[0], d0[1], d0[2], d0[3],
                             fah[mt][0], fah[mt][1], fah[mt][2], fah[mt][3],
                             fbh[p][0], fbh[p][1]);
                    mma_bf16(d0[0], d0[1], d0[2], d0[3],
                             fal[mt][0], fal[mt][1], fal[mt][2], fal[mt][3],
                             fbh[p][0], fbh[p][1]);
                    mma_bf16(d0[0], d0[1], d0[2], d0[3],
                             fah[mt][0], fah[mt][1], fah[mt][2], fah[mt][3],
                             fbl[p][0], fbl[p][1]);
                    mma_bf16(d1[0], d1[1], d1[2], d1[3],
                             fah[mt][0], fah[mt][1], fah[mt][2], fah[mt][3],
                             fbh[p][2], fbh[p][3]);
                    mma_bf16(d1[0], d1[1], d1[2], d1[3],
                             fal[mt][0], fal[mt][1], fal[mt][2], fal[mt][3],
                             fbh[p][2], fbh[p][3]);
                    mma_bf16(d1[0], d1[1], d1[2], d1[3],
                             fah[mt][0], fah[mt][1], fah[mt][2], fah[mt][3],
                             fbl[p][2], fbl[p][3]);
                }
            }
        }
        __syncthreads();
        buf ^= 1;
    }

    const int g = lane >> 2, tg = lane & 3;
#pragma unroll
    for (int mt = 0; mt < 2; mt++) {
#pragma unroll
        for (int nt = 0; nt < 4; nt++) {
            int m = m0 + wm * 32 + mt * 16 + g;
            int n = n0 + wn * 32 + nt * 8 + tg * 2;
            float b0 = bias ? bias[n] : 0.f;
            float b1 = bias ? bias[n + 1] : 0.f;
#pragma unroll
            for (int half = 0; half < 2; half++) {
                int mm = m + half * 8;
                size_t off = (size_t)mm * N + n;
                C[off]     += acc[mt][nt][half * 2 + 0] + b0;
                C[off + 1] += acc[mt][nt][half * 2 + 1] + b1;
            }
        }
    }
}

// ---------------- launch ----------------
static inline void split_launch(const float* src, __nv_bfloat16* hi, __nv_bfloat16* lo, size_t n) {
    int n4 = (int)(n / 4);
    split_kernel<<<(n4 + 255) / 256, 256>>>((const float4*)src, (__nv_bfloat162*)hi,
                                            (__nv_bfloat162*)lo, n4);
}

extern "C" void kernel_launch(void* const* d_in, const int* in_sizes, int n_in,
                              void* d_out, int out_size) {
    const float* emb    = (const float*)d_in[0];
    const float* norm_w = (const float*)d_in[1];
    const float* w_in   = (const float*)d_in[2];
    const float* b_in   = (const float*)d_in[3];
    const float* w_res  = (const float*)d_in[4];
    const float* b_res  = (const float*)d_in[5];
    const float* conv_w = (const float*)d_in[6];
    const float* conv_b = (const float*)d_in[7];
    const float* w_B    = (const float*)d_in[8];
    const float* b_B    = (const float*)d_in[9];
    const float* w_C    = (const float*)d_in[10];
    const float* b_C    = (const float*)d_in[11];
    const float* w_dt   = (const float*)d_in[12];
    const float* b_dt   = (const float*)d_in[13];
    const float* tau_dt = (const float*)d_in[14];
    const float* A_log  = (const float*)d_in[15];
    const float* Dp     = (const float*)d_in[16];
    const float* w_out  = (const float*)d_in[17];
    const float* b_out  = (const float*)d_in[18];
    const float* fnw    = (const float*)d_in[19];
    const int*   ids    = (const int*)d_in[20];
    float* out = (float*)d_out;

    cudaFuncSetAttribute(hgemm_kernel<0>, cudaFuncAttributeMaxDynamicSharedMemorySize, HG_SMEM);
    cudaFuncSetAttribute(hgemm_kernel<1>, cudaFuncAttributeMaxDynamicSharedMemorySize, HG_SMEM);
    cudaFuncSetAttribute(hgemm_kernel<3>, cudaFuncAttributeMaxDynamicSharedMemorySize, HG_SMEM);
    cudaFuncSetAttribute(hgemm64_acc_kernel, cudaFuncAttributeMaxDynamicSharedMemorySize, G64_SMEM);

    float *pX, *pH, *pRES, *pU, *pB, *pC, *pDT;
    cudaGetSymbolAddress((void**)&pX, g_X);
    cudaGetSymbolAddress((void**)&pH, g_H);
    cudaGetSymbolAddress((void**)&pRES, g_RES);
    cudaGetSymbolAddress((void**)&pU, g_U);
    cudaGetSymbolAddress((void**)&pB, g_B);
    cudaGetSymbolAddress((void**)&pC, g_C);
    cudaGetSymbolAddress((void**)&pDT, g_dt);

    __nv_bfloat16 *pXNh, *pXNl, *pHh, *pHl, *pYRh, *pYRl;
    __nv_bfloat16 *pWinh, *pWinl, *pWresh, *pWresl, *pWouth, *pWoutl, *pEmbh, *pEmbl;
    cudaGetSymbolAddress((void**)&pXNh, g_XNh);  cudaGetSymbolAddress((void**)&pXNl, g_XNl);
    cudaGetSymbolAddress((void**)&pHh, g_Hh);    cudaGetSymbolAddress((void**)&pHl, g_Hl);
    cudaGetSymbolAddress((void**)&pYRh, g_YRh);  cudaGetSymbolAddress((void**)&pYRl, g_YRl);
    cudaGetSymbolAddress((void**)&pWinh, g_Winh);   cudaGetSymbolAddress((void**)&pWinl, g_Winl);
    cudaGetSymbolAddress((void**)&pWresh, g_Wresh); cudaGetSymbolAddress((void**)&pWresl, g_Wresl);
    cudaGetSymbolAddress((void**)&pWouth, g_Wouth); cudaGetSymbolAddress((void**)&pWoutl, g_Woutl);
    cudaGetSymbolAddress((void**)&pEmbh, g_Embh);   cudaGetSymbolAddress((void**)&pEmbl, g_Embl);

    // weight conversions (all layers at once)
    split_launch(emb,   pEmbh,  pEmbl,  (size_t)VOCAB * D_MODEL);
    split_launch(w_in,  pWinh,  pWinl,  (size_t)N_LAYER * D_INNER * D_MODEL);
    split_launch(w_res, pWresh, pWresl, (size_t)N_LAYER * D_INNER * D_INNER);
    split_launch(w_out, pWouth, pWoutl, (size_t)N_LAYER * D_MODEL * D_INNER);

    embed_kernel<<<(M_ROWS * D_MODEL) / 256, 256>>>(emb, ids, pX);

    for (int i = 0; i < N_LAYER; i++) {
        const float* bi  = b_in   + (size_t)i * D_INNER;
        const float* br  = b_res  + (size_t)i * D_INNER;
        const float* cw  = conv_w + (size_t)i * D_INNER * D_CONV;
        const float* cb  = conv_b + (size_t)i * D_INNER;
        const float* wB  = w_B  + (size_t)i * D_STATE * D_INNER;
        const float* bB  = b_B  + (size_t)i * D_STATE;
        const float* wC  = w_C  + (size_t)i * D_STATE * D_INNER;
        const float* bC  = b_C  + (size_t)i * D_STATE;
        const float* wdt = w_dt + (size_t)i * D_INNER;
        const float* bdt = b_dt + (size_t)i;
        const float* tau = tau_dt + (size_t)i * D_INNER;
        const float* Al  = A_log + (size_t)i * D_INNER * D_STATE;
        const float* dp  = Dp    + (size_t)i * D_INNER;
        const float* bo  = b_out + (size_t)i * D_MODEL;
        const float* nw  = norm_w + (size_t)i * D_MODEL;
        const __nv_bfloat16* wih = pWinh  + (size_t)i * D_INNER * D_MODEL;
        const __nv_bfloat16* wil = pWinl  + (size_t)i * D_INNER * D_MODEL;
        const __nv_bfloat16* wrh = pWresh + (size_t)i * D_INNER * D_INNER;
        const __nv_bfloat16* wrl = pWresl + (size_t)i * D_INNER * D_INNER;
        const __nv_bfloat16* woh = pWouth + (size_t)i * D_MODEL * D_INNER;
        const __nv_bfloat16* wol = pWoutl + (size_t)i * D_MODEL * D_INNER;

        rmsnorm_kernel<<<M_ROWS, 256>>>(pX, nw, pXNh, pXNl);

        // in-proj: writes H fp32 + Hh/Hl bf16 split
        hgemm_kernel<3><<<dim3(D_INNER / HBN, M_ROWS / HBM), 256, HG_SMEM>>>(
            pXNh, pXNl, wih, wil, bi, pH, pHh, pHl, M_ROWS, D_INNER, D_MODEL);

        // res-proj + silu
        hgemm_kernel<1><<<dim3(D_INNER / HBN, M_ROWS / HBM), 256, HG_SMEM>>>(
            pHh, pHl, wrh, wrl, br, pRES, nullptr, nullptr, M_ROWS, D_INNER, D_INNER);

        conv_kernel<<<(M_ROWS * D_INNER) / 256, 256>>>(pH, cw, cb, pU);
        bc_kernel<<<M_ROWS, 256>>>(pU, wB, bB, wC, bC, wdt, bdt, pB, pC, pDT);

        scan_kernel<<<dim3(2 * D_INNER / 256, BATCH), 256>>>(
            pU, pRES, pB, pC, pDT, Al, tau, dp, pYRh, pYRl);

        // out-proj: accumulate into residual X — 128x64 tile for wave fill
        hgemm64_acc_kernel<<<dim3(D_MODEL / G64_BN, M_ROWS / HBM), 256, G64_SMEM>>>(
            pYRh, pYRl, woh, wol, bo, pX, M_ROWS, D_MODEL, D_INNER);
    }

    rmsnorm_kernel<<<M_ROWS, 256>>>(pX, fnw, pXNh, pXNl);

    hgemm_kernel<0><<<dim3(VOCAB / HBN, M_ROWS / HBM), 256, HG_SMEM>>>(
        pXNh, pXNl, pEmbh, pEmbl, nullptr, out, nullptr, nullptr, M_ROWS, VOCAB, D_MODEL);
}